// round 2
// baseline (speedup 1.0000x reference)
#include <cuda_runtime.h>
#include <cstdint>

#define N_NODES_MAX 250000

// Scratch (device globals — no allocation allowed)
__device__ float  g_deg [N_NODES_MAX];
__device__ float  g_dinv[N_NODES_MAX];
__device__ float4 g_xs1 [N_NODES_MAX * 4];   // layer-1 scaled features (16 f32/node)
__device__ float4 g_agg1[N_NODES_MAX * 4];   // layer-1 aggregation buffer
__device__ float4 g_xs2 [N_NODES_MAX];       // layer-2 scaled features (4 f32/node)

__device__ __forceinline__ void red_add_v4(float4* addr, float4 v) {
    unsigned long long ga = __cvta_generic_to_global(addr);
    asm volatile("red.global.add.v4.f32 [%0], {%1,%2,%3,%4};"
                 :: "l"(ga), "f"(v.x), "f"(v.y), "f"(v.z), "f"(v.w)
                 : "memory");
}

// ---------------- kernels ----------------

__global__ void k_deg_init(int n) {
    int i = blockIdx.x * blockDim.x + threadIdx.x;
    if (i < n) g_deg[i] = 1.0f;   // self-loop
}

__global__ void k_deg_count(const int* __restrict__ dst, int e) {
    int i = blockIdx.x * blockDim.x + threadIdx.x;
    if (i < e) {
        atomicAdd(&g_deg[dst[i]], 1.0f);
    }
}

// xw1 = x @ W1 ; xs1 = xw1 * dinv ; agg1 init = xs1 (self loop)
__global__ void k_node1(const float* __restrict__ x,
                        const float* __restrict__ W1, int n) {
    int i = blockIdx.x * blockDim.x + threadIdx.x;
    if (i >= n) return;
    float xi[5];
#pragma unroll
    for (int k = 0; k < 5; k++) xi[k] = x[i * 5 + k];
    float dinv = rsqrtf(g_deg[i]);
    g_dinv[i] = dinv;
#pragma unroll
    for (int q = 0; q < 4; q++) {
        float4 v;
        float* vp = &v.x;
#pragma unroll
        for (int c = 0; c < 4; c++) {
            int j = q * 4 + c;
            float acc = 0.f;
#pragma unroll
            for (int k = 0; k < 5; k++) acc = fmaf(xi[k], W1[k * 16 + j], acc);
            vp[c] = acc * dinv;
        }
        g_xs1[i * 4 + q]  = v;
        g_agg1[i * 4 + q] = v;
    }
}

__global__ void k_edge1(const int* __restrict__ src,
                        const int* __restrict__ dst, int e) {
    int i = blockIdx.x * blockDim.x + threadIdx.x;
    if (i >= e) return;
    int s = src[i];
    int d = dst[i];
#pragma unroll
    for (int q = 0; q < 4; q++) {
        float4 v = g_xs1[s * 4 + q];
        red_add_v4(&g_agg1[d * 4 + q], v);
    }
}

// h = relu(dinv*agg1 + b1); hw2 = h @ W2; xs2 = hw2*dinv; out init = xs2 (self loop)
__global__ void k_node2(const float* __restrict__ b1,
                        const float* __restrict__ W2,
                        float4* __restrict__ out, int n) {
    int i = blockIdx.x * blockDim.x + threadIdx.x;
    if (i >= n) return;
    float dinv = g_dinv[i];
    float h[16];
#pragma unroll
    for (int q = 0; q < 4; q++) {
        float4 a = g_agg1[i * 4 + q];
        const float* ap = &a.x;
#pragma unroll
        for (int c = 0; c < 4; c++) {
            int j = q * 4 + c;
            h[j] = fmaxf(fmaf(dinv, ap[c], b1[j]), 0.f);
        }
    }
    float4 v;
    float* vp = &v.x;
#pragma unroll
    for (int c = 0; c < 4; c++) {
        float acc = 0.f;
#pragma unroll
        for (int j = 0; j < 16; j++) acc = fmaf(h[j], W2[j * 4 + c], acc);
        vp[c] = acc * dinv;
    }
    g_xs2[i] = v;
    out[i]   = v;
}

__global__ void k_edge2(const int* __restrict__ src,
                        const int* __restrict__ dst,
                        float4* __restrict__ out, int e) {
    int i = blockIdx.x * blockDim.x + threadIdx.x;
    if (i >= e) return;
    int s = src[i];
    int d = dst[i];
    red_add_v4(&out[d], g_xs2[s]);
}

__global__ void k_node3(const float* __restrict__ b2,
                        float4* __restrict__ out, int n) {
    int i = blockIdx.x * blockDim.x + threadIdx.x;
    if (i >= n) return;
    float dinv = g_dinv[i];
    float4 v = out[i];
    float b0 = b2[0], bb1 = b2[1], bb2 = b2[2], bb3 = b2[3];
    v.x = fmaxf(fmaf(dinv, v.x, b0), 0.f);
    v.y = fmaxf(fmaf(dinv, v.y, bb1), 0.f);
    v.z = fmaxf(fmaf(dinv, v.z, bb2), 0.f);
    v.w = fmaxf(fmaf(dinv, v.w, bb3), 0.f);
    out[i] = v;
}

// ---------------- launch ----------------

extern "C" void kernel_launch(void* const* d_in, const int* in_sizes, int n_in,
                              void* d_out, int out_size) {
    const float* x  = (const float*)d_in[0];   // [N,5]
    const int*   ei = (const int*)d_in[1];     // [2,E] int32 (JAX x64 disabled)
    const float* W1 = (const float*)d_in[2];   // [5,16]
    const float* b1 = (const float*)d_in[3];   // [16]
    const float* W2 = (const float*)d_in[4];   // [16,4]
    const float* b2 = (const float*)d_in[5];   // [4]

    int n = in_sizes[0] / 5;
    int e = in_sizes[1] / 2;
    const int* src = ei;
    const int* dst = ei + e;

    float4* out = (float4*)d_out;

    const int BT = 256;
    int gn = (n + BT - 1) / BT;
    int ge = (e + BT - 1) / BT;

    k_deg_init <<<gn, BT>>>(n);
    k_deg_count<<<ge, BT>>>(dst, e);
    k_node1    <<<gn, BT>>>(x, W1, n);
    k_edge1    <<<ge, BT>>>(src, dst, e);
    k_node2    <<<gn, BT>>>(b1, W2, out, n);
    k_edge2    <<<ge, BT>>>(src, dst, out, e);
    k_node3    <<<gn, BT>>>(b2, out, n);
}

// round 3
// speedup vs baseline: 1.5946x; 1.5946x over previous
#include <cuda_runtime.h>
#include <cstdint>

#define N_NODES_MAX 250000

// Scratch (device globals — no allocation allowed)
__device__ float  g_deg  [N_NODES_MAX];
__device__ float  g_dinv [N_NODES_MAX];
__device__ float4 g_xsr  [N_NODES_MAX * 2];  // raw x * dinv, padded to 32B/node (5 of 8 floats used)
__device__ float4 g_agg1 [N_NODES_MAX * 2];  // layer-1 raw aggregation (5 of 8 floats used)
__device__ float4 g_xs2  [N_NODES_MAX];      // layer-2 scaled features (4 f32/node)

__device__ __forceinline__ void red_add_v4(float4* addr, float4 v) {
    unsigned long long ga = __cvta_generic_to_global(addr);
    asm volatile("red.global.add.v4.f32 [%0], {%1,%2,%3,%4};"
                 :: "l"(ga), "f"(v.x), "f"(v.y), "f"(v.z), "f"(v.w)
                 : "memory");
}
__device__ __forceinline__ void red_add_f32(float* addr, float v) {
    unsigned long long ga = __cvta_generic_to_global(addr);
    asm volatile("red.global.add.f32 [%0], %1;" :: "l"(ga), "f"(v) : "memory");
}

// ---------------- kernels ----------------

__global__ void k_deg_init(int n) {
    int i = blockIdx.x * blockDim.x + threadIdx.x;
    if (i < n) g_deg[i] = 1.0f;   // self-loop
}

// 4 edges per thread, vectorized dst load
__global__ void k_deg_count(const int4* __restrict__ dst4, int e4, const int* __restrict__ dst, int e) {
    int i = blockIdx.x * blockDim.x + threadIdx.x;
    if (i < e4) {
        int4 d = dst4[i];
        atomicAdd(&g_deg[d.x], 1.0f);
        atomicAdd(&g_deg[d.y], 1.0f);
        atomicAdd(&g_deg[d.z], 1.0f);
        atomicAdd(&g_deg[d.w], 1.0f);
    } else {
        int j = e4 * 4 + (i - e4);   // tail
        if (j < e && i - e4 < 4) atomicAdd(&g_deg[dst[j]], 1.0f);
    }
}

// dinv = rsqrt(deg); xsr = x*dinv (5 floats, padded); agg1 init = xsr (self loop)
__global__ void k_node1(const float* __restrict__ x, int n) {
    int i = blockIdx.x * blockDim.x + threadIdx.x;
    if (i >= n) return;
    float dinv = rsqrtf(g_deg[i]);
    g_dinv[i] = dinv;
    float4 a;
    a.x = x[i * 5 + 0] * dinv;
    a.y = x[i * 5 + 1] * dinv;
    a.z = x[i * 5 + 2] * dinv;
    a.w = x[i * 5 + 3] * dinv;
    float4 b;
    b.x = x[i * 5 + 4] * dinv;
    b.y = 0.f; b.z = 0.f; b.w = 0.f;
    g_xsr [i * 2]     = a;
    g_xsr [i * 2 + 1] = b;
    g_agg1[i * 2]     = a;
    g_agg1[i * 2 + 1] = b;
}

// layer-1 aggregation over raw 5-dim features
__global__ void k_edge1(const int* __restrict__ src,
                        const int* __restrict__ dst, int e) {
    int i = blockIdx.x * blockDim.x + threadIdx.x;
    if (i >= e) return;
    int s = src[i];
    int d = dst[i];
    float4 a = g_xsr[s * 2];
    float  b = g_xsr[s * 2 + 1].x;   // same 32B sector as a
    red_add_v4(&g_agg1[d * 2], a);
    red_add_f32(&g_agg1[d * 2 + 1].x, b);
}

// h = relu(dinv*(agg1raw @ W1) + b1); xs2 = (h @ W2)*dinv; out init = xs2 (self loop)
__global__ void k_node2(const float* __restrict__ W1,
                        const float* __restrict__ b1,
                        const float* __restrict__ W2,
                        float4* __restrict__ out, int n) {
    int i = blockIdx.x * blockDim.x + threadIdx.x;
    if (i >= n) return;
    float dinv = g_dinv[i];
    float4 a = g_agg1[i * 2];
    float4 bq = g_agg1[i * 2 + 1];
    float xa[5] = {a.x, a.y, a.z, a.w, bq.x};
    float h[16];
#pragma unroll
    for (int j = 0; j < 16; j++) {
        float acc = 0.f;
#pragma unroll
        for (int k = 0; k < 5; k++) acc = fmaf(xa[k], W1[k * 16 + j], acc);
        h[j] = fmaxf(fmaf(dinv, acc, b1[j]), 0.f);
    }
    float4 v;
    float* vp = &v.x;
#pragma unroll
    for (int c = 0; c < 4; c++) {
        float acc = 0.f;
#pragma unroll
        for (int j = 0; j < 16; j++) acc = fmaf(h[j], W2[j * 4 + c], acc);
        vp[c] = acc * dinv;
    }
    g_xs2[i] = v;
    out[i]   = v;
}

__global__ void k_edge2(const int* __restrict__ src,
                        const int* __restrict__ dst,
                        float4* __restrict__ out, int e) {
    int i = blockIdx.x * blockDim.x + threadIdx.x;
    if (i >= e) return;
    int s = src[i];
    int d = dst[i];
    red_add_v4(&out[d], g_xs2[s]);
}

__global__ void k_node3(const float* __restrict__ b2,
                        float4* __restrict__ out, int n) {
    int i = blockIdx.x * blockDim.x + threadIdx.x;
    if (i >= n) return;
    float dinv = g_dinv[i];
    float4 v = out[i];
    v.x = fmaxf(fmaf(dinv, v.x, b2[0]), 0.f);
    v.y = fmaxf(fmaf(dinv, v.y, b2[1]), 0.f);
    v.z = fmaxf(fmaf(dinv, v.z, b2[2]), 0.f);
    v.w = fmaxf(fmaf(dinv, v.w, b2[3]), 0.f);
    out[i] = v;
}

// ---------------- launch ----------------

extern "C" void kernel_launch(void* const* d_in, const int* in_sizes, int n_in,
                              void* d_out, int out_size) {
    const float* x  = (const float*)d_in[0];   // [N,5]
    const int*   ei = (const int*)d_in[1];     // [2,E] int32
    const float* W1 = (const float*)d_in[2];   // [5,16]
    const float* b1 = (const float*)d_in[3];   // [16]
    const float* W2 = (const float*)d_in[4];   // [16,4]
    const float* b2 = (const float*)d_in[5];   // [4]

    int n = in_sizes[0] / 5;
    int e = in_sizes[1] / 2;
    const int* src = ei;
    const int* dst = ei + e;

    float4* out = (float4*)d_out;

    const int BT = 256;
    int gn = (n + BT - 1) / BT;
    int ge = (e + BT - 1) / BT;

    int e4 = e / 4;
    int gdc = (e4 + 4 + BT - 1) / BT;   // extra threads for tail

    k_deg_init <<<gn, BT>>>(n);
    k_deg_count<<<gdc, BT>>>((const int4*)dst, e4, dst, e);
    k_node1    <<<gn, BT>>>(x, n);
    k_edge1    <<<ge, BT>>>(src, dst, e);
    k_node2    <<<gn, BT>>>(W1, b1, W2, out, n);
    k_edge2    <<<ge, BT>>>(src, dst, out, e);
    k_node3    <<<gn, BT>>>(b2, out, n);
}